// round 10
// baseline (speedup 1.0000x reference)
#include <cuda_runtime.h>
#include <cuda_fp16.h>
#include <math.h>

#define NN 100000
#define NE 3200000
#define DF 512
#define DH 64
#define NC 40

#define FULL 0xffffffffu

// ---------------- scratch (device globals) ----------------------------------
__device__ int     g_is64;
__device__ float   g_deg[NN];
__device__ float   g_dinv[NN];
__device__ int     g_cnt[NN];
__device__ int     g_rowptr[NN+1];
__device__ int     g_cursor[NN];
__device__ int2    g_edge[NE];
__device__ __half2 g_h1h[(size_t)NN*(DH/2)];   // h1 as fp16 pairs
__device__ float   g_agg1[(size_t)NN*DH];
__device__ __half2 g_h2h[(size_t)NN*(NC/2)];   // h2 as fp16 pairs

// ---------------- helpers -----------------------------------------------------
__device__ __forceinline__ unsigned smem_u32(const void* p) {
    unsigned a;
    asm("{ .reg .u64 t; cvta.to.shared.u64 t, %1; cvt.u32.u64 %0, t; }"
        : "=r"(a) : "l"(p));
    return a;
}

__device__ __forceinline__ unsigned to_tf32(float v) {
    unsigned r;
    asm("cvt.rna.tf32.f32 %0, %1;" : "=r"(r) : "f"(v));
    return r;
}

__device__ __forceinline__ void mma_tf32(float* d, const unsigned* a, const unsigned* b) {
    asm volatile("mma.sync.aligned.m16n8k8.row.col.f32.tf32.tf32.f32 "
        "{%0,%1,%2,%3}, {%4,%5,%6,%7}, {%8,%9}, {%0,%1,%2,%3};"
        : "+f"(d[0]), "+f"(d[1]), "+f"(d[2]), "+f"(d[3])
        : "r"(a[0]), "r"(a[1]), "r"(a[2]), "r"(a[3]), "r"(b[0]), "r"(b[1]));
}

__device__ __forceinline__ void cp16(unsigned dst, const void* src) {
    asm volatile("cp.async.cg.shared.global [%0], [%1], 16;"
                 :: "r"(dst), "l"(src) : "memory");
}

__device__ __forceinline__ int load_idx(const void* ei, size_t pos, int is64) {
    if (is64) return (int)((const long long*)ei)[pos];
    return ((const int*)ei)[pos];
}

// ---------------- init (+dtype detect in block 0) ---------------------------
__global__ void k_init(const int* __restrict__ ei32) {
    int i = blockIdx.x*blockDim.x + threadIdx.x;
    if (i < NN) { g_deg[i] = 1.0f; g_cnt[i] = 0; }
    if (blockIdx.x == 0) {
        __shared__ int nz;
        if (threadIdx.x == 0) nz = 0;
        __syncthreads();
        int local = 0;
        for (int s = threadIdx.x; s < 1024; s += blockDim.x)
            if (ei32[2*s + 1] != 0) local = 1;
        if (local) atomicOr(&nz, 1);
        __syncthreads();
        if (threadIdx.x == 0) g_is64 = (nz == 0) ? 1 : 0;
    }
}

__global__ void k_deg_hist(const void* __restrict__ ei,
                           const float* __restrict__ ew) {
    int e = blockIdx.x*blockDim.x + threadIdx.x;
    if (e >= NE) return;
    int is64 = g_is64;
    int c = load_idx(ei, (size_t)NE + e, is64);
    atomicAdd(&g_deg[c], ew[e]);
    atomicAdd(&g_cnt[c], 1);
}

// ---------------- dinv (all blocks) + scan (block 0) ------------------------
#define SCAN_T 1024
#define CHUNK  98
__global__ void __launch_bounds__(SCAN_T) k_dinv_scan() {
    int i = blockIdx.x*blockDim.x + threadIdx.x;
    if (i < NN) g_dinv[i] = rsqrtf(g_deg[i]);

    if (blockIdx.x == 0) {
        __shared__ int part[SCAN_T];
        int t = threadIdx.x;
        int lo = t * CHUNK;
        int hi = min(lo + CHUNK, NN);
        int sum = 0;
        for (int k = lo; k < hi; k++) sum += g_cnt[k];
        part[t] = sum;
        __syncthreads();
        #pragma unroll
        for (int off = 1; off < SCAN_T; off <<= 1) {
            int v = (t >= off) ? part[t-off] : 0;
            __syncthreads();
            part[t] += v;
            __syncthreads();
        }
        int run = (t > 0) ? part[t-1] : 0;
        for (int k = lo; k < hi; k++) {
            g_rowptr[k] = run;
            g_cursor[k] = run;
            run += g_cnt[k];
        }
        if (t == SCAN_T-1) g_rowptr[NN] = part[SCAN_T-1];
    }
}

__global__ void k_scatter(const void* __restrict__ ei,
                          const float* __restrict__ ew) {
    int e = blockIdx.x*blockDim.x + threadIdx.x;
    if (e >= NE) return;
    int is64 = g_is64;
    int r = load_idx(ei, (size_t)e, is64);
    int c = load_idx(ei, (size_t)NE + e, is64);
    float w = g_dinv[r] * ew[e] * g_dinv[c];
    int pos = atomicAdd(&g_cursor[c], 1);
    g_edge[pos] = make_int2(r, __float_as_int(w));
}

// ---------------- GEMM1: single-pass TF32, B direct from W1 -----------------
// CTA: 256 thr (8 warps: warpM 0-3, warpN 0-1), tile M=128 N=64, K chunks of 64.
// A smem [128 rows][68], B smem [64 k][72 n] (both conflict-free frag reads).
#define ASTR 68
#define BSTR 72
#define AFL  (128*ASTR)
#define BFL  (64*BSTR)
#define SM_TOT ((2*AFL + 2*BFL)*4)

__global__ void __launch_bounds__(256) k_gemm1_tf32(const float* __restrict__ x,
                                                    const float* __restrict__ W1) {
    extern __shared__ float smem[];
    unsigned sbase = smem_u32(smem);
    int tid = threadIdx.x;
    int wid = tid >> 5, lane = tid & 31;
    int warpM = wid >> 1, warpN = wid & 1;
    int g = lane >> 2, tig = lane & 3;
    int row0 = blockIdx.x * 128;

    int ar = tid >> 4, aq = tid & 15;   // A: 2048 float4s, 8/thread
    int br = tid >> 4, bq = tid & 15;   // B: 1024 float4s, 4/thread

    // prefetch chunk 0 into buffer 0
    {
        #pragma unroll
        for (int i = 0; i < 8; i++) {
            int r = ar + i*16;
            int grow = min(row0 + r, NN-1);
            cp16(sbase + (r*ASTR + aq*4)*4,
                 (const void*)&x[(size_t)grow*DF + aq*4]);
        }
        #pragma unroll
        for (int i = 0; i < 4; i++) {
            int r = br + i*16;   // k-row within chunk
            cp16(sbase + (2*AFL + r*BSTR + bq*4)*4,
                 (const void*)&W1[(size_t)r*DH + bq*4]);
        }
        asm volatile("cp.async.commit_group;" ::: "memory");
    }

    float acc[2][4][4];
    #pragma unroll
    for (int mt = 0; mt < 2; mt++)
        #pragma unroll
        for (int nt = 0; nt < 4; nt++)
            #pragma unroll
            for (int q = 0; q < 4; q++) acc[mt][nt][q] = 0.f;

    for (int ch = 0; ch < 8; ch++) {
        int cur = ch & 1;
        if (ch < 7) {
            int nxt = (ch+1) & 1;
            int koff = (ch+1)*64;
            #pragma unroll
            for (int i = 0; i < 8; i++) {
                int r = ar + i*16;
                int grow = min(row0 + r, NN-1);
                cp16(sbase + (nxt*AFL + r*ASTR + aq*4)*4,
                     (const void*)&x[(size_t)grow*DF + koff + aq*4]);
            }
            #pragma unroll
            for (int i = 0; i < 4; i++) {
                int r = br + i*16;
                cp16(sbase + (2*AFL + nxt*BFL + r*BSTR + bq*4)*4,
                     (const void*)&W1[(size_t)(koff + r)*DH + bq*4]);
            }
            asm volatile("cp.async.commit_group;" ::: "memory");
            asm volatile("cp.async.wait_group 1;" ::: "memory");
        } else {
            asm volatile("cp.async.wait_group 0;" ::: "memory");
        }
        __syncthreads();

        const float* sA = smem + cur*AFL;
        const float* sB = smem + 2*AFL + cur*BFL;

        #pragma unroll
        for (int ks = 0; ks < 8; ks++) {
            int k0 = ks*8;
            unsigned aH[2][4], bH[4][2];
            #pragma unroll
            for (int mt = 0; mt < 2; mt++) {
                int rb = warpM*32 + mt*16;
                aH[mt][0] = to_tf32(sA[(rb+g  )*ASTR + k0+tig  ]);
                aH[mt][1] = to_tf32(sA[(rb+g+8)*ASTR + k0+tig  ]);
                aH[mt][2] = to_tf32(sA[(rb+g  )*ASTR + k0+tig+4]);
                aH[mt][3] = to_tf32(sA[(rb+g+8)*ASTR + k0+tig+4]);
            }
            #pragma unroll
            for (int nt = 0; nt < 4; nt++) {
                int n = warpN*32 + nt*8 + g;
                bH[nt][0] = to_tf32(sB[(k0+tig  )*BSTR + n]);
                bH[nt][1] = to_tf32(sB[(k0+tig+4)*BSTR + n]);
            }
            #pragma unroll
            for (int mt = 0; mt < 2; mt++)
                #pragma unroll
                for (int nt = 0; nt < 4; nt++)
                    mma_tf32(acc[mt][nt], aH[mt], bH[nt]);
        }
        __syncthreads();
    }

    // epilogue: D frag (g, 2*tig) -> g_h1h (fp16 pairs)
    #pragma unroll
    for (int mt = 0; mt < 2; mt++) {
        #pragma unroll
        for (int half = 0; half < 2; half++) {
            int grow = row0 + warpM*32 + mt*16 + g + half*8;
            if (grow < NN) {
                __half2* dst = &g_h1h[(size_t)grow*(DH/2) + warpN*16 + tig];
                #pragma unroll
                for (int nt = 0; nt < 4; nt++)
                    dst[nt*4] = __floats2half2_rn(acc[mt][nt][half*2],
                                                  acc[mt][nt][half*2+1]);
            }
        }
    }
}

// ---------------- CSR aggregation layer 1: 2 edges per warp in flight --------
// half-warp h processes edge 2j+h; lane sub (0..15) covers 4 features (uint2).
__global__ void k_agg1() {
    int warp = (blockIdx.x*blockDim.x + threadIdx.x) >> 5;
    if (warp >= NN) return;
    int lane = threadIdx.x & 31;
    int half = lane >> 4;
    int sub  = lane & 15;

    int start = g_rowptr[warp];
    int end   = g_rowptr[warp+1];
    float s = g_dinv[warp]; s *= s;

    const uint2* h1 = (const uint2*)g_h1h;    // 16 uint2 per row
    float4 acc = make_float4(0.f, 0.f, 0.f, 0.f);
    {
        uint2 v = h1[(size_t)warp*16 + sub];
        float2 f0 = __half22float2(*(__half2*)&v.x);
        float2 f1 = __half22float2(*(__half2*)&v.y);
        if (half == 0) {
            acc.x = s*f0.x; acc.y = s*f0.y; acc.z = s*f1.x; acc.w = s*f1.y;
        }
    }

    int2 eb = (start + lane < end) ? g_edge[start + lane] : make_int2(0, 0);
    for (int base = start; base < end; base += 32) {
        int n = min(32, end - base);
        int2 ebn = (base + 32 + lane < end) ? g_edge[base + 32 + lane]
                                            : make_int2(0, 0);
        #pragma unroll
        for (int jj = 0; jj < 16; jj++) {
            int idx = jj*2 + half;
            int   s2 = __shfl_sync(FULL, eb.x, idx);
            float wj = __int_as_float(__shfl_sync(FULL, eb.y, idx));
            if (idx < n) {
                uint2 v = h1[(size_t)s2*16 + sub];
                float2 f0 = __half22float2(*(__half2*)&v.x);
                float2 f1 = __half22float2(*(__half2*)&v.y);
                acc.x += wj*f0.x; acc.y += wj*f0.y;
                acc.z += wj*f1.x; acc.w += wj*f1.y;
            }
        }
        eb = ebn;
    }

    acc.x += __shfl_down_sync(FULL, acc.x, 16);
    acc.y += __shfl_down_sync(FULL, acc.y, 16);
    acc.z += __shfl_down_sync(FULL, acc.z, 16);
    acc.w += __shfl_down_sync(FULL, acc.w, 16);
    if (half == 0)
        *(float4*)&g_agg1[(size_t)warp*DH + sub*4] = acc;
}

// ---------------- h2 = relu(agg1 + b1) @ W2  (fp16 output) ------------------
__global__ void k_relu_gemm2(const float* __restrict__ b1,
                             const float* __restrict__ W2) {
    __shared__ float sW2[DH*NC];
    __shared__ float sb1[DH];
    int tid = threadIdx.x;
    for (int i = tid; i < DH*NC; i += blockDim.x) sW2[i] = W2[i];
    if (tid < DH) sb1[tid] = b1[tid];
    __syncthreads();

    int row = blockIdx.x*blockDim.x + tid;
    if (row >= NN) return;

    float h[DH];
    const float4* av = (const float4*)&g_agg1[(size_t)row*DH];
    #pragma unroll
    for (int q = 0; q < DH/4; q++) {
        float4 v = av[q];
        h[q*4+0] = fmaxf(v.x + sb1[q*4+0], 0.f);
        h[q*4+1] = fmaxf(v.y + sb1[q*4+1], 0.f);
        h[q*4+2] = fmaxf(v.z + sb1[q*4+2], 0.f);
        h[q*4+3] = fmaxf(v.w + sb1[q*4+3], 0.f);
    }

    #pragma unroll
    for (int cc = 0; cc < NC; cc += 8) {
        float acc[8];
        #pragma unroll
        for (int j = 0; j < 8; j++) acc[j] = 0.f;
        #pragma unroll 8
        for (int k = 0; k < DH; k++) {
            float hk = h[k];
            const float4* wv = (const float4*)&sW2[k*NC + cc];
            float4 w0 = wv[0], w1 = wv[1];
            acc[0] += hk * w0.x; acc[1] += hk * w0.y;
            acc[2] += hk * w0.z; acc[3] += hk * w0.w;
            acc[4] += hk * w1.x; acc[5] += hk * w1.y;
            acc[6] += hk * w1.z; acc[7] += hk * w1.w;
        }
        __half2* dst = &g_h2h[(size_t)row*(NC/2) + cc/2];
        dst[0] = __floats2half2_rn(acc[0], acc[1]);
        dst[1] = __floats2half2_rn(acc[2], acc[3]);
        dst[2] = __floats2half2_rn(acc[4], acc[5]);
        dst[3] = __floats2half2_rn(acc[6], acc[7]);
    }
}

// ---------------- CSR agg layer 2 + bias + log_softmax: 3 edges in flight ----
// group g (lanes 10g..10g+9) processes edge 3j+g; lane sub covers 4 classes.
__global__ void k_agg2_softmax(const float* __restrict__ b2,
                               float* __restrict__ out) {
    int warp = (blockIdx.x*blockDim.x + threadIdx.x) >> 5;
    if (warp >= NN) return;
    int lane = threadIdx.x & 31;
    int grp = lane / 10;          // 0,1,2 active; 3 = lanes 30,31 idle
    int sub = lane - grp*10;
    bool act = grp < 3;

    int start = g_rowptr[warp];
    int end   = g_rowptr[warp+1];
    float s = g_dinv[warp]; s *= s;

    const uint2* h2 = (const uint2*)g_h2h;    // 10 uint2 per row
    float4 acc = make_float4(0.f, 0.f, 0.f, 0.f);
    if (act) {
        uint2 v = h2[(size_t)warp*10 + sub];
        float2 f0 = __half22float2(*(__half2*)&v.x);
        float2 f1 = __half22float2(*(__half2*)&v.y);
        if (grp == 0) {
            acc.x = s*f0.x; acc.y = s*f0.y; acc.z = s*f1.x; acc.w = s*f1.y;
        }
    }

    int2 eb = (lane < 30 && start + lane < end) ? g_edge[start + lane]
                                                : make_int2(0, 0);
    for (int base = start; base < end; base += 30) {
        int n = min(30, end - base);
        int2 ebn = (lane < 30 && base + 30 + lane < end)
                       ? g_edge[base + 30 + lane] : make_int2(0, 0);
        #pragma unroll
        for (int jj = 0; jj < 10; jj++) {
            int idx = jj*3 + grp;
            int   s2 = __shfl_sync(FULL, eb.x, idx & 31);
            float wj = __int_as_float(__shfl_sync(FULL, eb.y, idx & 31));
            if (act && idx < n) {
                uint2 v = h2[(size_t)s2*10 + sub];
                float2 f0 = __half22float2(*(__half2*)&v.x);
                float2 f1 = __half22float2(*(__half2*)&v.y);
                acc.x += wj*f0.x; acc.y += wj*f0.y;
                acc.z += wj*f1.x; acc.w += wj*f1.y;
            }
        }
        eb = ebn;
    }

    // combine groups 1,2 into group 0 (lanes 0..9)
    acc.x += __shfl_down_sync(FULL, acc.x, 10) + __shfl_down_sync(FULL, acc.x, 20);
    acc.y += __shfl_down_sync(FULL, acc.y, 10) + __shfl_down_sync(FULL, acc.y, 20);
    acc.z += __shfl_down_sync(FULL, acc.z, 10) + __shfl_down_sync(FULL, acc.z, 20);
    acc.w += __shfl_down_sync(FULL, acc.w, 10) + __shfl_down_sync(FULL, acc.w, 20);

    bool own = (lane < 10);
    if (own) {
        float4 bv = *(const float4*)&b2[sub*4];
        acc.x += bv.x; acc.y += bv.y; acc.z += bv.z; acc.w += bv.w;
    }

    // softmax over 40 logits distributed on lanes 0..9 (butterfly over 16)
    float m = own ? fmaxf(fmaxf(acc.x, acc.y), fmaxf(acc.z, acc.w)) : -1e30f;
    #pragma unroll
    for (int off = 8; off > 0; off >>= 1)
        m = fmaxf(m, __shfl_xor_sync(FULL, m, off));

    float es = own ? (expf(acc.x-m) + expf(acc.y-m) + expf(acc.z-m) + expf(acc.w-m))
                   : 0.f;
    #pragma unroll
    for (int off = 8; off > 0; off >>= 1)
        es += __shfl_xor_sync(FULL, es, off);

    float lse = m + logf(es);

    if (own) {
        *(float4*)&out[(size_t)warp*NC + sub*4] =
            make_float4(acc.x - lse, acc.y - lse, acc.z - lse, acc.w - lse);
    }
}

extern "C" void kernel_launch(void* const* d_in, const int* in_sizes, int n_in,
                              void* d_out, int out_size) {
    const float* x  = (const float*)d_in[0];
    const void*  ei = d_in[1];
    const float* ew = (const float*)d_in[2];
    const float* W1 = (const float*)d_in[3];
    const float* b1 = (const float*)d_in[4];
    const float* W2 = (const float*)d_in[5];
    const float* b2 = (const float*)d_in[6];
    float* out = (float*)d_out;

    cudaFuncSetAttribute(k_gemm1_tf32, cudaFuncAttributeMaxDynamicSharedMemorySize, SM_TOT);

    int warpGrid = (NN*32 + 255) / 256;

    // 4th launch = ncu capture slot -> k_scatter this round.
    k_init         <<<(NN+255)/256, 256>>>((const int*)ei);
    k_deg_hist     <<<(NE+255)/256, 256>>>(ei, ew);
    k_dinv_scan    <<<(NN+SCAN_T-1)/SCAN_T, SCAN_T>>>();
    k_scatter      <<<(NE+255)/256, 256>>>(ei, ew);
    k_gemm1_tf32   <<<(NN+127)/128, 256, SM_TOT>>>(x, W1);
    k_agg1         <<<warpGrid, 256>>>();
    k_relu_gemm2   <<<(NN+255)/256, 256>>>(b1, W2);
    k_agg2_softmax <<<warpGrid, 256>>>(b2, out);
}

// round 11
// speedup vs baseline: 1.0304x; 1.0304x over previous
#include <cuda_runtime.h>
#include <cuda_fp16.h>
#include <math.h>

#define NN 100000
#define NE 3200000
#define DF 512
#define DH 64
#define NC 40

#define FULL 0xffffffffu

// ---------------- scratch (device globals) ----------------------------------
__device__ int     g_is64;
__device__ float   g_deg[NN];
__device__ int     g_cnt[NN];
__device__ int     g_rowptr[NN+1];
__device__ int     g_cursor[NN];
__device__ int2    g_edge[NE];                 // (src, bitcast(ew)) sorted by dst
__device__ __half2 g_h1h[(size_t)NN*(DH/2)];   // h1' = dinv*h1, fp16 pairs
__device__ float   g_agg1[(size_t)NN*DH];
__device__ __half2 g_h2h[(size_t)NN*(NC/2)];   // h2' = dinv*h2, fp16 pairs

// ---------------- helpers -----------------------------------------------------
__device__ __forceinline__ unsigned smem_u32(const void* p) {
    unsigned a;
    asm("{ .reg .u64 t; cvta.to.shared.u64 t, %1; cvt.u32.u64 %0, t; }"
        : "=r"(a) : "l"(p));
    return a;
}

__device__ __forceinline__ unsigned to_tf32(float v) {
    unsigned r;
    asm("cvt.rna.tf32.f32 %0, %1;" : "=r"(r) : "f"(v));
    return r;
}

__device__ __forceinline__ void mma_tf32(float* d, const unsigned* a, const unsigned* b) {
    asm volatile("mma.sync.aligned.m16n8k8.row.col.f32.tf32.tf32.f32 "
        "{%0,%1,%2,%3}, {%4,%5,%6,%7}, {%8,%9}, {%0,%1,%2,%3};"
        : "+f"(d[0]), "+f"(d[1]), "+f"(d[2]), "+f"(d[3])
        : "r"(a[0]), "r"(a[1]), "r"(a[2]), "r"(a[3]), "r"(b[0]), "r"(b[1]));
}

__device__ __forceinline__ void cp16(unsigned dst, const void* src) {
    asm volatile("cp.async.cg.shared.global [%0], [%1], 16;"
                 :: "r"(dst), "l"(src) : "memory");
}

__device__ __forceinline__ int load_idx(const void* ei, size_t pos, int is64) {
    if (is64) return (int)((const long long*)ei)[pos];
    return ((const int*)ei)[pos];
}

// ---------------- init (+dtype detect in block 0) ---------------------------
__global__ void k_init(const int* __restrict__ ei32) {
    int i = blockIdx.x*blockDim.x + threadIdx.x;
    if (i < NN) { g_deg[i] = 1.0f; g_cnt[i] = 0; }
    if (blockIdx.x == 0) {
        __shared__ int nz;
        if (threadIdx.x == 0) nz = 0;
        __syncthreads();
        int local = 0;
        for (int s = threadIdx.x; s < 1024; s += blockDim.x)
            if (ei32[2*s + 1] != 0) local = 1;
        if (local) atomicOr(&nz, 1);
        __syncthreads();
        if (threadIdx.x == 0) g_is64 = (nz == 0) ? 1 : 0;
    }
}

// ---------------- cnt histogram (dst degree counts only) --------------------
__global__ void k_cnt_hist(const void* __restrict__ ei) {
    int e = blockIdx.x*blockDim.x + threadIdx.x;
    if (e >= NE) return;
    int is64 = g_is64;
    int c = load_idx(ei, (size_t)NE + e, is64);
    atomicAdd(&g_cnt[c], 1);
}

// ---------------- single-block scan of g_cnt --------------------------------
#define SCAN_T 1024
#define CHUNK  98
__global__ void __launch_bounds__(SCAN_T) k_scan() {
    __shared__ int part[SCAN_T];
    int t = threadIdx.x;
    int lo = t * CHUNK;
    int hi = min(lo + CHUNK, NN);
    int sum = 0;
    for (int k = lo; k < hi; k++) sum += g_cnt[k];
    part[t] = sum;
    __syncthreads();
    #pragma unroll
    for (int off = 1; off < SCAN_T; off <<= 1) {
        int v = (t >= off) ? part[t-off] : 0;
        __syncthreads();
        part[t] += v;
        __syncthreads();
    }
    int run = (t > 0) ? part[t-1] : 0;
    for (int k = lo; k < hi; k++) {
        g_rowptr[k] = run;
        g_cursor[k] = run;
        run += g_cnt[k];
    }
    if (t == SCAN_T-1) g_rowptr[NN] = part[SCAN_T-1];
}

// ---------------- scatter edges into CSR + accumulate weighted degree -------
__global__ void k_scatter(const void* __restrict__ ei,
                          const float* __restrict__ ew) {
    int e = blockIdx.x*blockDim.x + threadIdx.x;
    if (e >= NE) return;
    int is64 = g_is64;
    int r = load_idx(ei, (size_t)e, is64);
    int c = load_idx(ei, (size_t)NE + e, is64);
    float w = ew[e];
    int pos = atomicAdd(&g_cursor[c], 1);
    g_edge[pos] = make_int2(r, __float_as_int(w));
    atomicAdd(&g_deg[c], w);
}

// ---------------- GEMM1: single-pass TF32; epilogue scales by dinv ----------
// CTA: 256 thr (8 warps: warpM 0-3, warpN 0-1), tile M=128 N=64, K chunks of 64.
#define ASTR 68
#define BSTR 72
#define AFL  (128*ASTR)
#define BFL  (64*BSTR)
#define SM_TOT ((2*AFL + 2*BFL)*4)

__global__ void __launch_bounds__(256) k_gemm1_tf32(const float* __restrict__ x,
                                                    const float* __restrict__ W1) {
    extern __shared__ float smem[];
    unsigned sbase = smem_u32(smem);
    int tid = threadIdx.x;
    int wid = tid >> 5, lane = tid & 31;
    int warpM = wid >> 1, warpN = wid & 1;
    int g = lane >> 2, tig = lane & 3;
    int row0 = blockIdx.x * 128;

    int ar = tid >> 4, aq = tid & 15;
    int br = tid >> 4, bq = tid & 15;

    {
        #pragma unroll
        for (int i = 0; i < 8; i++) {
            int r = ar + i*16;
            int grow = min(row0 + r, NN-1);
            cp16(sbase + (r*ASTR + aq*4)*4,
                 (const void*)&x[(size_t)grow*DF + aq*4]);
        }
        #pragma unroll
        for (int i = 0; i < 4; i++) {
            int r = br + i*16;
            cp16(sbase + (2*AFL + r*BSTR + bq*4)*4,
                 (const void*)&W1[(size_t)r*DH + bq*4]);
        }
        asm volatile("cp.async.commit_group;" ::: "memory");
    }

    float acc[2][4][4];
    #pragma unroll
    for (int mt = 0; mt < 2; mt++)
        #pragma unroll
        for (int nt = 0; nt < 4; nt++)
            #pragma unroll
            for (int q = 0; q < 4; q++) acc[mt][nt][q] = 0.f;

    for (int ch = 0; ch < 8; ch++) {
        int cur = ch & 1;
        if (ch < 7) {
            int nxt = (ch+1) & 1;
            int koff = (ch+1)*64;
            #pragma unroll
            for (int i = 0; i < 8; i++) {
                int r = ar + i*16;
                int grow = min(row0 + r, NN-1);
                cp16(sbase + (nxt*AFL + r*ASTR + aq*4)*4,
                     (const void*)&x[(size_t)grow*DF + koff + aq*4]);
            }
            #pragma unroll
            for (int i = 0; i < 4; i++) {
                int r = br + i*16;
                cp16(sbase + (2*AFL + nxt*BFL + r*BSTR + bq*4)*4,
                     (const void*)&W1[(size_t)(koff + r)*DH + bq*4]);
            }
            asm volatile("cp.async.commit_group;" ::: "memory");
            asm volatile("cp.async.wait_group 1;" ::: "memory");
        } else {
            asm volatile("cp.async.wait_group 0;" ::: "memory");
        }
        __syncthreads();

        const float* sA = smem + cur*AFL;
        const float* sB = smem + 2*AFL + cur*BFL;

        #pragma unroll
        for (int ks = 0; ks < 8; ks++) {
            int k0 = ks*8;
            unsigned aH[2][4], bH[4][2];
            #pragma unroll
            for (int mt = 0; mt < 2; mt++) {
                int rb = warpM*32 + mt*16;
                aH[mt][0] = to_tf32(sA[(rb+g  )*ASTR + k0+tig  ]);
                aH[mt][1] = to_tf32(sA[(rb+g+8)*ASTR + k0+tig  ]);
                aH[mt][2] = to_tf32(sA[(rb+g  )*ASTR + k0+tig+4]);
                aH[mt][3] = to_tf32(sA[(rb+g+8)*ASTR + k0+tig+4]);
            }
            #pragma unroll
            for (int nt = 0; nt < 4; nt++) {
                int n = warpN*32 + nt*8 + g;
                bH[nt][0] = to_tf32(sB[(k0+tig  )*BSTR + n]);
                bH[nt][1] = to_tf32(sB[(k0+tig+4)*BSTR + n]);
            }
            #pragma unroll
            for (int mt = 0; mt < 2; mt++)
                #pragma unroll
                for (int nt = 0; nt < 4; nt++)
                    mma_tf32(acc[mt][nt], aH[mt], bH[nt]);
        }
        __syncthreads();
    }

    // epilogue: h1' = dinv(row) * (x@W1) -> fp16 pairs
    #pragma unroll
    for (int mt = 0; mt < 2; mt++) {
        #pragma unroll
        for (int half = 0; half < 2; half++) {
            int grow = row0 + warpM*32 + mt*16 + g + half*8;
            if (grow < NN) {
                float di = rsqrtf(g_deg[grow]);
                __half2* dst = &g_h1h[(size_t)grow*(DH/2) + warpN*16 + tig];
                #pragma unroll
                for (int nt = 0; nt < 4; nt++)
                    dst[nt*4] = __floats2half2_rn(di*acc[mt][nt][half*2],
                                                  di*acc[mt][nt][half*2+1]);
            }
        }
    }
}

// ---------------- CSR agg layer 1: agg1[c] = dinv[c]*(h1'[c] + sum ew*h1'[r])
__global__ void k_agg1() {
    int warp = (blockIdx.x*blockDim.x + threadIdx.x) >> 5;
    if (warp >= NN) return;
    int lane = threadIdx.x & 31;

    int start = g_rowptr[warp];
    int end   = g_rowptr[warp+1];

    float2 acc = __half22float2(g_h1h[(size_t)warp*(DH/2) + lane]);

    int2 eb = (start + lane < end) ? g_edge[start + lane] : make_int2(0, 0);
    for (int base = start; base < end; base += 32) {
        int n = min(32, end - base);
        int2 ebn = (base + 32 + lane < end) ? g_edge[base + 32 + lane]
                                            : make_int2(0, 0);
        #pragma unroll 8
        for (int j = 0; j < n; j++) {
            int   s2 = __shfl_sync(FULL, eb.x, j);
            float wj = __int_as_float(__shfl_sync(FULL, eb.y, j));
            float2 hv = __half22float2(g_h1h[(size_t)s2*(DH/2) + lane]);
            acc.x += wj * hv.x;
            acc.y += wj * hv.y;
        }
        eb = ebn;
    }
    float di = rsqrtf(g_deg[warp]);
    *(float2*)&g_agg1[(size_t)warp*DH + lane*2] = make_float2(di*acc.x, di*acc.y);
}

// ---------------- h2' = dinv * (relu(agg1 + b1) @ W2)  (fp16 output) --------
__global__ void k_relu_gemm2(const float* __restrict__ b1,
                             const float* __restrict__ W2) {
    __shared__ float sW2[DH*NC];
    __shared__ float sb1[DH];
    int tid = threadIdx.x;
    for (int i = tid; i < DH*NC; i += blockDim.x) sW2[i] = W2[i];
    if (tid < DH) sb1[tid] = b1[tid];
    __syncthreads();

    int row = blockIdx.x*blockDim.x + tid;
    if (row >= NN) return;

    float h[DH];
    const float4* av = (const float4*)&g_agg1[(size_t)row*DH];
    #pragma unroll
    for (int q = 0; q < DH/4; q++) {
        float4 v = av[q];
        h[q*4+0] = fmaxf(v.x + sb1[q*4+0], 0.f);
        h[q*4+1] = fmaxf(v.y + sb1[q*4+1], 0.f);
        h[q*4+2] = fmaxf(v.z + sb1[q*4+2], 0.f);
        h[q*4+3] = fmaxf(v.w + sb1[q*4+3], 0.f);
    }
    float di = rsqrtf(g_deg[row]);

    #pragma unroll
    for (int cc = 0; cc < NC; cc += 8) {
        float acc[8];
        #pragma unroll
        for (int j = 0; j < 8; j++) acc[j] = 0.f;
        #pragma unroll 8
        for (int k = 0; k < DH; k++) {
            float hk = h[k];
            const float4* wv = (const float4*)&sW2[k*NC + cc];
            float4 w0 = wv[0], w1 = wv[1];
            acc[0] += hk * w0.x; acc[1] += hk * w0.y;
            acc[2] += hk * w0.z; acc[3] += hk * w0.w;
            acc[4] += hk * w1.x; acc[5] += hk * w1.y;
            acc[6] += hk * w1.z; acc[7] += hk * w1.w;
        }
        __half2* dst = &g_h2h[(size_t)row*(NC/2) + cc/2];
        dst[0] = __floats2half2_rn(di*acc[0], di*acc[1]);
        dst[1] = __floats2half2_rn(di*acc[2], di*acc[3]);
        dst[2] = __floats2half2_rn(di*acc[4], di*acc[5]);
        dst[3] = __floats2half2_rn(di*acc[6], di*acc[7]);
    }
}

// ---------------- CSR agg layer 2 + bias + log_softmax ----------------------
// lanes 0..19 each own class pair {2*lane, 2*lane+1}
__global__ void k_agg2_softmax(const float* __restrict__ b2,
                               float* __restrict__ out) {
    int warp = (blockIdx.x*blockDim.x + threadIdx.x) >> 5;
    if (warp >= NN) return;
    int lane = threadIdx.x & 31;
    bool act = lane < (NC/2);

    int start = g_rowptr[warp];
    int end   = g_rowptr[warp+1];

    float a0 = 0.f, a1 = 0.f;
    if (act) {
        float2 self = __half22float2(g_h2h[(size_t)warp*(NC/2) + lane]);
        a0 = self.x; a1 = self.y;
    }

    int2 eb = (start + lane < end) ? g_edge[start + lane] : make_int2(0, 0);
    for (int base = start; base < end; base += 32) {
        int n = min(32, end - base);
        int2 ebn = (base + 32 + lane < end) ? g_edge[base + 32 + lane]
                                            : make_int2(0, 0);
        #pragma unroll 8
        for (int j = 0; j < n; j++) {
            int   s2 = __shfl_sync(FULL, eb.x, j);
            float wj = __int_as_float(__shfl_sync(FULL, eb.y, j));
            if (act) {
                float2 hv = __half22float2(g_h2h[(size_t)s2*(NC/2) + lane]);
                a0 += wj * hv.x;
                a1 += wj * hv.y;
            }
        }
        eb = ebn;
    }

    if (act) {
        float di = rsqrtf(g_deg[warp]);
        a0 = di*a0 + b2[lane*2];
        a1 = di*a1 + b2[lane*2 + 1];
    }

    float m = act ? fmaxf(a0, a1) : -1e30f;
    #pragma unroll
    for (int off = 16; off > 0; off >>= 1)
        m = fmaxf(m, __shfl_xor_sync(FULL, m, off));

    float es = act ? (expf(a0 - m) + expf(a1 - m)) : 0.f;
    #pragma unroll
    for (int off = 16; off > 0; off >>= 1)
        es += __shfl_xor_sync(FULL, es, off);

    float lse = m + logf(es);

    if (act) {
        *(float2*)&out[(size_t)warp*NC + lane*2] = make_float2(a0 - lse, a1 - lse);
    }
}

extern "C" void kernel_launch(void* const* d_in, const int* in_sizes, int n_in,
                              void* d_out, int out_size) {
    const float* x  = (const float*)d_in[0];
    const void*  ei = d_in[1];
    const float* ew = (const float*)d_in[2];
    const float* W1 = (const float*)d_in[3];
    const float* b1 = (const float*)d_in[4];
    const float* W2 = (const float*)d_in[5];
    const float* b2 = (const float*)d_in[6];
    float* out = (float*)d_out;

    cudaFuncSetAttribute(k_gemm1_tf32, cudaFuncAttributeMaxDynamicSharedMemorySize, SM_TOT);

    int warpGrid = (NN*32 + 255) / 256;

    // 4th launch = ncu capture slot -> k_scatter (verifies L2-transaction cut).
    k_init         <<<(NN+255)/256, 256>>>((const int*)ei);
    k_cnt_hist     <<<(NE+255)/256, 256>>>(ei);
    k_scan         <<<1, SCAN_T>>>();
    k_scatter      <<<(NE+255)/256, 256>>>(ei, ew);
    k_gemm1_tf32   <<<(NN+127)/128, 256, SM_TOT>>>(x, W1);
    k_agg1         <<<warpGrid, 256>>>();
    k_relu_gemm2   <<<(NN+255)/256, 256>>>(b1, W2);
    k_agg2_softmax <<<warpGrid, 256>>>(b2, out);
}